// round 1
// baseline (speedup 1.0000x reference)
#include <cuda_runtime.h>
#include <cuda_bf16.h>
#include <math.h>
#include <stdint.h>

#define BB 128
#define NP 8732
#define NO 16
#define NC 21

// ---------------- scratch (static __device__; no allocation allowed) ----------------
__device__ float              g_best_overlap[(size_t)BB * NP];
__device__ int                g_best_tidx[(size_t)BB * NP];
__device__ unsigned long long g_best_prior[BB * NO];
__device__ float              g_hnm[(size_t)BB * NP];
__device__ int                g_numpos[BB];
__device__ double             g_loss_l;
__device__ double             g_loss_c;

// ---------------- helpers ----------------
__device__ __forceinline__ unsigned long long warp_max_u64(unsigned long long v) {
#pragma unroll
    for (int o = 16; o > 0; o >>= 1) {
        unsigned long long w = __shfl_down_sync(0xffffffffu, v, o);
        v = (w > v) ? w : v;
    }
    return v;
}

__device__ __forceinline__ double warp_sum_d(double v) {
#pragma unroll
    for (int o = 16; o > 0; o >>= 1)
        v += __shfl_down_sync(0xffffffffu, v, o);
    return v;
}

__device__ __forceinline__ unsigned warp_sum_u(unsigned v) {
#pragma unroll
    for (int o = 16; o > 0; o >>= 1)
        v += __shfl_down_sync(0xffffffffu, v, o);
    return v;
}

// ---------------- K0: init accumulators ----------------
__global__ void k_init() {
    int i = blockIdx.x * blockDim.x + threadIdx.x;
    if (i < BB * NO) g_best_prior[i] = 0ULL;
    if (i < BB) g_numpos[i] = 0;
    if (i == 0) { g_loss_l = 0.0; g_loss_c = 0.0; }
}

// ---------------- K1: jaccard match ----------------
// grid: (ceil(NP/256), BB), block 256
__global__ void k_match(const float* __restrict__ dbox,
                        const float* __restrict__ targets) {
    __shared__ float st[NO][5];   // x1,y1,x2,y2,area
    __shared__ unsigned long long sbest[NO];
    const int b = blockIdx.y;
    const int tid = threadIdx.x;

    if (tid < NO) {
        const float* tr = targets + ((size_t)b * NO + tid) * 5;
        float x1 = tr[0], y1 = tr[1], x2 = tr[2], y2 = tr[3];
        st[tid][0] = x1; st[tid][1] = y1; st[tid][2] = x2; st[tid][3] = y2;
        st[tid][4] = (x2 - x1) * (y2 - y1);
        sbest[tid] = 0ULL;
    }
    __syncthreads();

    const int p = blockIdx.x * blockDim.x + tid;
    float px1 = 0.f, py1 = 0.f, px2 = 0.f, py2 = 0.f, pa = 0.f;
    if (p < NP) {
        float cx = dbox[p * 4 + 0], cy = dbox[p * 4 + 1];
        float w  = dbox[p * 4 + 2], h  = dbox[p * 4 + 3];
        px1 = cx - w * 0.5f; py1 = cy - h * 0.5f;
        px2 = cx + w * 0.5f; py2 = cy + h * 0.5f;
        pa  = (px2 - px1) * (py2 - py1);   // exactly what point_form-derived area is
    }
    float bestv = -1.0f;
    int   bestt = 0;
    const unsigned inv_p = ~(unsigned)p;

#pragma unroll
    for (int t = 0; t < NO; t++) {
        float ix1 = fmaxf(st[t][0], px1);
        float iy1 = fmaxf(st[t][1], py1);
        float ix2 = fminf(st[t][2], px2);
        float iy2 = fminf(st[t][3], py2);
        float iw = fmaxf(ix2 - ix1, 0.f);
        float ih = fmaxf(iy2 - iy1, 0.f);
        float inter = iw * ih;
        float iou = (p < NP) ? inter / (st[t][4] + pa - inter) : 0.f;
        if (iou > bestv) { bestv = iou; bestt = t; }   // strict >: first-index tiebreak
        // per-truth argmax over priors: pack (iou_bits, ~p) so max => highest iou, lowest p
        unsigned long long key =
            ((unsigned long long)__float_as_uint(iou) << 32) | (unsigned long long)inv_p;
        key = warp_max_u64(key);
        if ((tid & 31) == 0) atomicMax(&sbest[t], key);
    }

    if (p < NP) {
        g_best_overlap[(size_t)b * NP + p] = bestv;
        g_best_tidx[(size_t)b * NP + p]    = bestt;
    }
    __syncthreads();
    if (tid < NO) atomicMax(&g_best_prior[b * NO + tid], sbest[tid]);
}

// ---------------- K2: scatter override (last write wins, in truth order) ----------------
__global__ void k_override() {
    int b = threadIdx.x;
    if (b < BB) {
        for (int t = 0; t < NO; t++) {
            unsigned long long key = g_best_prior[b * NO + t];
            unsigned p = ~(unsigned)(key & 0xffffffffu);
            g_best_overlap[(size_t)b * NP + p] = 2.0f;
            g_best_tidx[(size_t)b * NP + p]    = t;
        }
    }
}

// ---------------- K3: main loss (CE + smooth-L1 on positives) ----------------
// grid: (ceil(NP/256), BB), block 256
__global__ void k_loss(const float* __restrict__ loc_data,
                       const float* __restrict__ conf_data,
                       const float* __restrict__ dbox,
                       const float* __restrict__ targets) {
    __shared__ float st[NO][4];
    __shared__ int   slab[NO];
    __shared__ double s_ll[8], s_lc[8];
    __shared__ unsigned s_np[8];

    const int b = blockIdx.y;
    const int tid = threadIdx.x;

    if (tid < NO) {
        const float* tr = targets + ((size_t)b * NO + tid) * 5;
        st[tid][0] = tr[0]; st[tid][1] = tr[1];
        st[tid][2] = tr[2]; st[tid][3] = tr[3];
        slab[tid] = (int)tr[4];
    }
    __syncthreads();

    const int p = blockIdx.x * blockDim.x + tid;
    double l_l = 0.0, l_c = 0.0;
    unsigned npos = 0;

    if (p < NP) {
        const size_t ip = (size_t)b * NP + p;
        float ov = g_best_overlap[ip];
        int   t  = g_best_tidx[ip];
        bool  pos = (ov >= 0.5f);
        int   conf = pos ? (slab[t] + 1) : 0;

        // log-softmax CE over 21 classes (row is 84 contiguous bytes -> coalesced)
        const float* cr = conf_data + ip * NC;
        float v[NC];
#pragma unroll
        for (int i = 0; i < NC; i++) v[i] = cr[i];
        float m = v[0];
#pragma unroll
        for (int i = 1; i < NC; i++) m = fmaxf(m, v[i]);
        float s = 0.f;
#pragma unroll
        for (int i = 0; i < NC; i++) s += expf(v[i] - m);
        float ce = logf(s) + m - v[conf];

        g_hnm[ip] = pos ? 0.f : ce;

        if (pos) {
            npos = 1;
            l_c = (double)ce;
            float cx = dbox[p * 4 + 0], cy = dbox[p * 4 + 1];
            float w  = dbox[p * 4 + 2], h  = dbox[p * 4 + 3];
            float mx1 = st[t][0], my1 = st[t][1], mx2 = st[t][2], my2 = st[t][3];
            float lt0 = ((mx1 + mx2) * 0.5f - cx) / (0.1f * w);
            float lt1 = ((my1 + my2) * 0.5f - cy) / (0.1f * h);
            float lt2 = logf((mx2 - mx1) / w) / 0.2f;
            float lt3 = logf((my2 - my1) / h) / 0.2f;
            const float* ld = loc_data + ip * 4;
            float ltv[4] = {lt0, lt1, lt2, lt3};
            float acc = 0.f;
#pragma unroll
            for (int i = 0; i < 4; i++) {
                float d  = ld[i] - ltv[i];
                float ad = fabsf(d);
                acc += (ad < 1.0f) ? 0.5f * d * d : (ad - 0.5f);
            }
            l_l = (double)acc;
        }
    }

    // block reduce
    double wll = warp_sum_d(l_l);
    double wlc = warp_sum_d(l_c);
    unsigned wnp = warp_sum_u(npos);
    int warp = tid >> 5, lane = tid & 31;
    if (lane == 0) { s_ll[warp] = wll; s_lc[warp] = wlc; s_np[warp] = wnp; }
    __syncthreads();
    if (tid == 0) {
        double tll = 0.0, tlc = 0.0; unsigned tnp = 0;
        for (int w = 0; w < 8; w++) { tll += s_ll[w]; tlc += s_lc[w]; tnp += s_np[w]; }
        if (tll != 0.0) atomicAdd(&g_loss_l, tll);
        if (tlc != 0.0) atomicAdd(&g_loss_c, tlc);
        if (tnp) atomicAdd(&g_numpos[b], (int)tnp);
    }
}

// ---------------- K4: hard negative mining — sum of top-K of hnm, per batch ----------------
// grid: BB blocks, 256 threads. Sort-free: radix binary search on float bits (all >= 0).
__global__ void k_topk() {
    __shared__ float sv[NP];
    __shared__ unsigned scnt[8];
    __shared__ unsigned s_tot;
    __shared__ double s_sum[8];

    const int b = blockIdx.x;
    const int tid = threadIdx.x;
    const int warp = tid >> 5, lane = tid & 31;

    for (int i = tid; i < NP; i += blockDim.x)
        sv[i] = g_hnm[(size_t)b * NP + i];
    const int K = min(3 * g_numpos[b], NP);
    __syncthreads();
    if (K <= 0) return;

    // find bits of K-th largest value
    unsigned T = 0;
    for (int bit = 31; bit >= 0; bit--) {
        unsigned cand = T | (1u << bit);
        unsigned c = 0;
        for (int i = tid; i < NP; i += blockDim.x)
            c += (__float_as_uint(sv[i]) >= cand) ? 1u : 0u;
        c = warp_sum_u(c);
        if (lane == 0) scnt[warp] = c;
        __syncthreads();
        if (tid == 0) {
            unsigned tot = 0;
            for (int w = 0; w < 8; w++) tot += scnt[w];
            s_tot = tot;
        }
        __syncthreads();
        if (s_tot >= (unsigned)K) T = cand;
        __syncthreads();
    }

    // sum of strictly-greater values + tie correction
    double sum = 0.0;
    unsigned cgt = 0;
    for (int i = tid; i < NP; i += blockDim.x) {
        unsigned u = __float_as_uint(sv[i]);
        if (u > T) { sum += (double)sv[i]; cgt++; }
    }
    sum = warp_sum_d(sum);
    cgt = warp_sum_u(cgt);
    if (lane == 0) { s_sum[warp] = sum; scnt[warp] = cgt; }
    __syncthreads();
    if (tid == 0) {
        double tsum = 0.0; unsigned tcgt = 0;
        for (int w = 0; w < 8; w++) { tsum += s_sum[w]; tcgt += scnt[w]; }
        tsum += (double)((unsigned)K - tcgt) * (double)__uint_as_float(T);
        atomicAdd(&g_loss_c, tsum);
    }
}

// ---------------- K5: finalize ----------------
__global__ void k_fin(float* __restrict__ out) {
    if (threadIdx.x == 0 && blockIdx.x == 0) {
        int n = 0;
        for (int b = 0; b < BB; b++) n += g_numpos[b];
        double N = (double)n;
        out[0] = (float)(g_loss_l / N);
        out[1] = (float)(g_loss_c / N);
    }
}

// ---------------- launch ----------------
extern "C" void kernel_launch(void* const* d_in, const int* in_sizes, int n_in,
                              void* d_out, int out_size) {
    const float* loc_data  = (const float*)d_in[0];
    const float* conf_data = (const float*)d_in[1];
    const float* dbox      = (const float*)d_in[2];
    const float* targets   = (const float*)d_in[3];
    float* out = (float*)d_out;

    const int threads = 256;
    const int pblocks = (NP + threads - 1) / threads;

    k_init<<<(BB * NO + 255) / 256, 256>>>();
    k_match<<<dim3(pblocks, BB), threads>>>(dbox, targets);
    k_override<<<1, BB>>>();
    k_loss<<<dim3(pblocks, BB), threads>>>(loc_data, conf_data, dbox, targets);
    k_topk<<<BB, 256>>>();
    k_fin<<<1, 32>>>(out);
}

// round 2
// speedup vs baseline: 1.0460x; 1.0460x over previous
#include <cuda_runtime.h>
#include <cuda_bf16.h>
#include <math.h>
#include <stdint.h>

#define BB 128
#define NP 8732
#define NO 16
#define NC 21
#define PBLK 256
#define NXB ((NP + PBLK - 1) / PBLK)   // 35

// ---------------- scratch (static __device__; zero-initialized at load) ----------------
__device__ unsigned long long g_best_prior[BB * NO];   // reset by k_override each run
__device__ unsigned char      g_code[(size_t)BB * NP]; // t+1 if positive else 0
__device__ float              g_hnm[(size_t)BB * NP];
__device__ int                g_numpos[BB];            // reset by k_fin each run
__device__ double             g_loss_l;                // reset by k_fin each run
__device__ double             g_loss_c;                // reset by k_fin each run

// ---------------- helpers ----------------
__device__ __forceinline__ double warp_sum_d(double v) {
#pragma unroll
    for (int o = 16; o > 0; o >>= 1)
        v += __shfl_down_sync(0xffffffffu, v, o);
    return v;
}
__device__ __forceinline__ unsigned warp_sum_u(unsigned v) {
#pragma unroll
    for (int o = 16; o > 0; o >>= 1)
        v += __shfl_down_sync(0xffffffffu, v, o);
    return v;
}

// ---------------- K1: jaccard match ----------------
// grid (NXB, BB), block 256
__global__ void k_match(const float4* __restrict__ dbox4,
                        const float* __restrict__ targets) {
    __shared__ float4 stb[NO];
    __shared__ float  sarea[NO];
    __shared__ unsigned long long sbest[NO];
    const int b = blockIdx.y;
    const int tid = threadIdx.x;

    if (tid < NO) {
        const float* tr = targets + ((size_t)b * NO + tid) * 5;
        float x1 = tr[0], y1 = tr[1], x2 = tr[2], y2 = tr[3];
        stb[tid] = make_float4(x1, y1, x2, y2);
        sarea[tid] = (x2 - x1) * (y2 - y1);
        sbest[tid] = 0ULL;
    }
    __syncthreads();

    const int p = blockIdx.x * PBLK + tid;
    if (p < NP) {
        float4 d = dbox4[p];
        float px1 = d.x - d.z * 0.5f, py1 = d.y - d.w * 0.5f;
        float px2 = d.x + d.z * 0.5f, py2 = d.y + d.w * 0.5f;
        float pa = (px2 - px1) * (py2 - py1);
        float bestv = -1.0f;
        int   bestt = 0;
        const unsigned long long invp = (unsigned long long)(~(unsigned)p);

#pragma unroll
        for (int t = 0; t < NO; t++) {
            float4 tb = stb[t];
            float iw = fminf(tb.z, px2) - fmaxf(tb.x, px1);
            float ih = fminf(tb.w, py2) - fmaxf(tb.y, py1);
            iw = fmaxf(iw, 0.0f);
            ih = fmaxf(ih, 0.0f);
            float inter = iw * ih;
            float iou = inter / (sarea[t] + pa - inter);   // precise div (threshold-sensitive)
            if (iou > bestv) { bestv = iou; bestt = t; }   // strict >: first-index tiebreak
            // per-truth argmax over priors: (iou_bits, ~p): max => highest iou, then lowest p
            unsigned long long key = ((unsigned long long)__float_as_uint(iou) << 32) | invp;
            if (key > sbest[t]) atomicMax(&sbest[t], key); // monotonic filter; stale read ok
        }
        g_code[(size_t)b * NP + p] = (bestv >= 0.5f) ? (unsigned char)(bestt + 1) : 0;
    }
    __syncthreads();
    if (tid < NO && sbest[tid]) atomicMax(&g_best_prior[b * NO + tid], sbest[tid]);
}

// ---------------- K2: scatter override (last write wins, in truth order) ----------------
// grid BB blocks, 32 threads (only thread 0 works; t-order must be serial per batch)
__global__ void k_override() {
    if (threadIdx.x == 0) {
        const int b = blockIdx.x;
        for (int t = 0; t < NO; t++) {
            unsigned long long key = g_best_prior[b * NO + t];
            unsigned p = ~(unsigned)(key & 0xffffffffu);
            g_code[(size_t)b * NP + p] = (unsigned char)(t + 1);
            g_best_prior[b * NO + t] = 0ULL;   // reset for next replay
        }
    }
}

// ---------------- K3: main loss (CE + smooth-L1 on positives) ----------------
// grid (NXB, BB), block 256
__global__ void k_loss(const float4* __restrict__ loc4,
                       const float* __restrict__ conf,
                       const float4* __restrict__ dbox4,
                       const float* __restrict__ targets) {
    __shared__ __align__(16) float sconf[PBLK * NC];   // 21504 B
    __shared__ float4 stb[NO];
    __shared__ int    slab[NO];
    __shared__ double s_ll[8], s_lc[8];
    __shared__ unsigned s_np[8];

    const int b = blockIdx.y;
    const int tid = threadIdx.x;
    const int p0 = blockIdx.x * PBLK;
    const int nrows = min(PBLK, NP - p0);

    if (tid < NO) {
        const float* tr = targets + ((size_t)b * NO + tid) * 5;
        stb[tid] = make_float4(tr[0], tr[1], tr[2], tr[3]);
        slab[tid] = (int)tr[4];
    }

    // stage conf tile through smem, coalesced float4 (tile start is 16B-aligned)
    const size_t base = ((size_t)b * NP + p0) * NC;
    if (nrows == PBLK) {
        const float4* src = (const float4*)(conf + base);
        float4* dst = (float4*)sconf;
        for (int i = tid; i < PBLK * NC / 4; i += PBLK)
            dst[i] = src[i];
    } else {
        for (int i = tid; i < nrows * NC; i += PBLK)
            sconf[i] = conf[base + i];
    }
    __syncthreads();

    double l_l = 0.0, l_c = 0.0;
    unsigned npos = 0;

    if (tid < nrows) {
        const int p = p0 + tid;
        const size_t ip = (size_t)b * NP + p;
        const int code = g_code[ip];
        const bool pos = (code != 0);
        const int t = code - 1;
        const int cls = pos ? (slab[t] + 1) : 0;

        const float* v = sconf + tid * NC;   // stride 21 (odd) -> bank-conflict-free
        float m = v[0];
#pragma unroll
        for (int i = 1; i < NC; i++) m = fmaxf(m, v[i]);
        float s = 0.0f;
#pragma unroll
        for (int i = 0; i < NC; i++) s += __expf(v[i] - m);
        float ce = __logf(s) + m - v[cls];

        g_hnm[ip] = pos ? 0.0f : ce;

        if (pos) {
            npos = 1;
            l_c = (double)ce;
            float4 d = dbox4[p];
            float4 tb = stb[t];
            float lt0 = ((tb.x + tb.z) * 0.5f - d.x) / (0.1f * d.z);
            float lt1 = ((tb.y + tb.w) * 0.5f - d.y) / (0.1f * d.w);
            float lt2 = __logf((tb.z - tb.x) / d.z) / 0.2f;
            float lt3 = __logf((tb.w - tb.y) / d.w) / 0.2f;
            float4 ld = loc4[ip];
            float dv[4] = {ld.x - lt0, ld.y - lt1, ld.z - lt2, ld.w - lt3};
            float acc = 0.0f;
#pragma unroll
            for (int i = 0; i < 4; i++) {
                float ad = fabsf(dv[i]);
                acc += (ad < 1.0f) ? 0.5f * dv[i] * dv[i] : (ad - 0.5f);
            }
            l_l = (double)acc;
        }
    }

    double wll = warp_sum_d(l_l);
    double wlc = warp_sum_d(l_c);
    unsigned wnp = warp_sum_u(npos);
    const int warp = tid >> 5, lane = tid & 31;
    if (lane == 0) { s_ll[warp] = wll; s_lc[warp] = wlc; s_np[warp] = wnp; }
    __syncthreads();
    if (tid == 0) {
        double tll = 0.0, tlc = 0.0; unsigned tnp = 0;
        for (int w = 0; w < 8; w++) { tll += s_ll[w]; tlc += s_lc[w]; tnp += s_np[w]; }
        if (tll != 0.0) atomicAdd(&g_loss_l, tll);
        if (tlc != 0.0) atomicAdd(&g_loss_c, tlc);
        if (tnp) atomicAdd(&g_numpos[b], (int)tnp);
    }
}

// ---------------- K4: top-K sum via 4-pass radix-256 select ----------------
// grid BB blocks, 256 threads
__global__ void k_topk() {
    __shared__ float sv[NP];                 // 34928 B
    __shared__ unsigned hist[256];
    __shared__ unsigned wsuf[8];
    __shared__ unsigned s_B, s_Krem;
    __shared__ unsigned scnt[8];
    __shared__ double s_sum[8];

    const int b = blockIdx.x;
    const int tid = threadIdx.x;
    const int lane = tid & 31, warp = tid >> 5;

    for (int i = tid; i < NP; i += 256)
        sv[i] = g_hnm[(size_t)b * NP + i];
    const int K = min(3 * g_numpos[b], NP);
    __syncthreads();
    if (K <= 0) return;

    unsigned prefix = 0;
    unsigned Krem = (unsigned)K;

    for (int pass = 0; pass < 4; pass++) {
        const int shift = 24 - pass * 8;
        hist[tid] = 0;
        __syncthreads();

        // histogram of candidates (matching current prefix), warp-aggregated atomics
        for (int i = tid; i < NXB * PBLK; i += 256) {
            bool valid = (i < NP);
            unsigned u = valid ? __float_as_uint(sv[i]) : 0u;
            bool match = valid && (pass == 0 || (u >> (shift + 8)) == prefix);
            unsigned bin = match ? ((u >> shift) & 0xFFu) : 0xFFFFu;
            unsigned mk = __match_any_sync(0xffffffffu, bin);
            if (match && lane == (__ffs(mk) - 1))
                atomicAdd(&hist[bin], (unsigned)__popc(mk));
        }
        __syncthreads();

        // exclusive suffix count per bin
        unsigned v = hist[tid];
        unsigned s = v;
#pragma unroll
        for (int off = 1; off < 32; off <<= 1) {
            unsigned w = __shfl_down_sync(0xffffffffu, s, off);
            if (lane + off < 32) s += w;
        }
        if (lane == 0) wsuf[warp] = s;    // warp totals
        __syncthreads();
        if (tid == 0) {
            unsigned acc = 0;
            for (int w = 7; w >= 0; w--) { unsigned t2 = wsuf[w]; wsuf[w] = acc; acc += t2; }
        }
        __syncthreads();
        unsigned exc = (s - v) + wsuf[warp];        // count of candidates in bins > tid
        if (exc < Krem && Krem <= exc + v) { s_B = (unsigned)tid; s_Krem = Krem - exc; }
        __syncthreads();
        prefix = (prefix << 8) | s_B;
        Krem = s_Krem;
    }

    // prefix = float bits of the K-th largest value T (all hnm >= 0 -> uint-ordered)
    const unsigned T = prefix;
    double sum = 0.0;
    unsigned cgt = 0;
    for (int i = tid; i < NP; i += 256) {
        unsigned u = __float_as_uint(sv[i]);
        if (u > T) { sum += (double)sv[i]; cgt++; }
    }
    sum = warp_sum_d(sum);
    cgt = warp_sum_u(cgt);
    if (lane == 0) { s_sum[warp] = sum; scnt[warp] = cgt; }
    __syncthreads();
    if (tid == 0) {
        double tsum = 0.0; unsigned tcgt = 0;
        for (int w = 0; w < 8; w++) { tsum += s_sum[w]; tcgt += scnt[w]; }
        tsum += (double)((unsigned)K - tcgt) * (double)__uint_as_float(T);
        atomicAdd(&g_loss_c, tsum);
    }
}

// ---------------- K5: finalize + reset accumulators for next replay ----------------
__global__ void k_fin(float* __restrict__ out) {
    __shared__ int ssum[4];
    const int tid = threadIdx.x;   // 128 threads
    int n = g_numpos[tid];
    g_numpos[tid] = 0;
    unsigned un = warp_sum_u((unsigned)n);
    if ((tid & 31) == 0) ssum[tid >> 5] = (int)un;
    __syncthreads();
    if (tid == 0) {
        int tot = ssum[0] + ssum[1] + ssum[2] + ssum[3];
        double N = (double)tot;
        out[0] = (float)(g_loss_l / N);
        out[1] = (float)(g_loss_c / N);
        g_loss_l = 0.0;
        g_loss_c = 0.0;
    }
}

// ---------------- launch ----------------
extern "C" void kernel_launch(void* const* d_in, const int* in_sizes, int n_in,
                              void* d_out, int out_size) {
    const float4* loc4     = (const float4*)d_in[0];
    const float*  conf     = (const float*)d_in[1];
    const float4* dbox4    = (const float4*)d_in[2];
    const float*  targets  = (const float*)d_in[3];
    float* out = (float*)d_out;

    k_match<<<dim3(NXB, BB), PBLK>>>(dbox4, targets);
    k_override<<<BB, 32>>>();
    k_loss<<<dim3(NXB, BB), PBLK>>>(loc4, conf, dbox4, targets);
    k_topk<<<BB, 256>>>();
    k_fin<<<1, BB>>>(out);
}

// round 3
// speedup vs baseline: 1.3345x; 1.2758x over previous
#include <cuda_runtime.h>
#include <cuda_bf16.h>
#include <math.h>
#include <stdint.h>

#define BB 128
#define NP 8732
#define NO 16
#define NC 21
#define PBLK 256
#define NXB ((NP + PBLK - 1) / PBLK)   // 35
#define TKT 1024                        // k_topk threads
#define EPT ((NP + TKT - 1) / TKT)      // 9 elements per thread

// ---------------- scratch (static __device__; zero-initialized at load) ----------------
__device__ unsigned long long g_best_prior[BB * NO];   // reset by k_topk each run
__device__ unsigned char      g_code[(size_t)BB * NP]; // t+1 if positive else 0
__device__ float              g_hnm[(size_t)BB * NP];
__device__ int                g_numpos[BB];            // reset by k_fin each run
__device__ double             g_loss_l;                // reset by k_fin each run
__device__ double             g_loss_c;                // reset by k_fin each run

// ---------------- helpers ----------------
__device__ __forceinline__ double warp_sum_d(double v) {
#pragma unroll
    for (int o = 16; o > 0; o >>= 1)
        v += __shfl_down_sync(0xffffffffu, v, o);
    return v;
}
__device__ __forceinline__ unsigned warp_sum_u(unsigned v) {
#pragma unroll
    for (int o = 16; o > 0; o >>= 1)
        v += __shfl_down_sync(0xffffffffu, v, o);
    return v;
}

// ---------------- K1: jaccard match ----------------
// grid (NXB, BB), block 256
__global__ void k_match(const float4* __restrict__ dbox4,
                        const float* __restrict__ targets) {
    __shared__ float4 stb[NO];
    __shared__ float  sarea[NO];
    __shared__ unsigned long long sbest[NO];
    const int b = blockIdx.y;
    const int tid = threadIdx.x;
    const int lane = tid & 31;

    if (tid < NO) {
        const float* tr = targets + ((size_t)b * NO + tid) * 5;
        float x1 = tr[0], y1 = tr[1], x2 = tr[2], y2 = tr[3];
        stb[tid] = make_float4(x1, y1, x2, y2);
        sarea[tid] = (x2 - x1) * (y2 - y1);
        sbest[tid] = 0ULL;
    }
    __syncthreads();

    const int p = blockIdx.x * PBLK + tid;
    const bool valid = (p < NP);
    const int pc = valid ? p : (NP - 1);
    float4 d = dbox4[pc];
    float px1 = d.x - d.z * 0.5f, py1 = d.y - d.w * 0.5f;
    float px2 = d.x + d.z * 0.5f, py2 = d.y + d.w * 0.5f;
    float pa = (px2 - px1) * (py2 - py1);
    float bestv = -1.0f;
    int   bestt = 0;
    // invalid lanes can never win: ioubits forced 0, invp forced 0 (key==0 filtered)
    const unsigned long long invp = valid ? (unsigned long long)(~(unsigned)p) : 0ULL;

#pragma unroll
    for (int t = 0; t < NO; t++) {
        float4 tb = stb[t];
        float iw = fminf(tb.z, px2) - fmaxf(tb.x, px1);
        float ih = fminf(tb.w, py2) - fmaxf(tb.y, py1);
        iw = fmaxf(iw, 0.0f);
        ih = fmaxf(ih, 0.0f);
        float inter = iw * ih;
        float iou = inter / (sarea[t] + pa - inter);
        if (iou > bestv) { bestv = iou; bestt = t; }   // strict >: first-index tiebreak
        unsigned ioubits = valid ? __float_as_uint(iou) : 0u;
        unsigned wmax = __reduce_max_sync(0xffffffffu, ioubits);
        unsigned ball = __ballot_sync(0xffffffffu, ioubits == wmax);
        if (lane == __ffs(ball) - 1) {   // leader = lowest lane (= lowest p) among ties
            unsigned long long key = ((unsigned long long)wmax << 32) | invp;
            if (key > sbest[t]) atomicMax(&sbest[t], key);
        }
    }
    if (valid)
        g_code[(size_t)b * NP + p] = (bestv >= 0.5f) ? (unsigned char)(bestt + 1) : 0;
    __syncthreads();
    if (tid < NO && sbest[tid]) atomicMax(&g_best_prior[b * NO + tid], sbest[tid]);
}

// ---------------- K2: main loss (override folded in; CE + smooth-L1) ----------------
// grid (NXB, BB), block 256
__global__ void k_loss(const float4* __restrict__ loc4,
                       const float* __restrict__ conf,
                       const float4* __restrict__ dbox4,
                       const float* __restrict__ targets) {
    __shared__ __align__(16) float sconf[PBLK * NC];   // 21504 B
    __shared__ float4 stb[NO];
    __shared__ int    slab[NO];
    __shared__ int    sprior[NO];
    __shared__ double s_ll[8], s_lc[8];
    __shared__ unsigned s_np[8];

    const int b = blockIdx.y;
    const int tid = threadIdx.x;
    const int p0 = blockIdx.x * PBLK;
    const int nrows = min(PBLK, NP - p0);

    if (tid < NO) {
        const float* tr = targets + ((size_t)b * NO + tid) * 5;
        stb[tid] = make_float4(tr[0], tr[1], tr[2], tr[3]);
        slab[tid] = (int)tr[4];
        unsigned long long key = g_best_prior[b * NO + tid];
        sprior[tid] = (int)(~(unsigned)(key & 0xffffffffu));
    }

    // stage conf tile through smem, coalesced float4 (tile start is 16B-aligned)
    const size_t base = ((size_t)b * NP + p0) * NC;
    if (nrows == PBLK) {
        const float4* src = (const float4*)(conf + base);
        float4* dst = (float4*)sconf;
        for (int i = tid; i < PBLK * NC / 4; i += PBLK)
            dst[i] = src[i];
    } else {
        for (int i = tid; i < nrows * NC; i += PBLK)
            sconf[i] = conf[base + i];
    }
    __syncthreads();

    double l_l = 0.0, l_c = 0.0;
    unsigned npos = 0;

    if (tid < nrows) {
        const int p = p0 + tid;
        const size_t ip = (size_t)b * NP + p;
        int code = g_code[ip];
        // override: best prior per truth is forced positive; ascending t => last wins
#pragma unroll
        for (int t = 0; t < NO; t++)
            if (sprior[t] == p) code = t + 1;
        const bool pos = (code != 0);
        const int t = code - 1;
        const int cls = pos ? (slab[t] + 1) : 0;

        const float* v = sconf + tid * NC;   // stride 21 (odd) -> bank-conflict-free
        float m = v[0];
#pragma unroll
        for (int i = 1; i < NC; i++) m = fmaxf(m, v[i]);
        float s = 0.0f;
#pragma unroll
        for (int i = 0; i < NC; i++) s += __expf(v[i] - m);
        float ce = __logf(s) + m - v[cls];

        g_hnm[ip] = pos ? 0.0f : ce;

        if (pos) {
            npos = 1;
            l_c = (double)ce;
            float4 d = dbox4[p];
            float4 tb = stb[t];
            float lt0 = ((tb.x + tb.z) * 0.5f - d.x) / (0.1f * d.z);
            float lt1 = ((tb.y + tb.w) * 0.5f - d.y) / (0.1f * d.w);
            float lt2 = __logf((tb.z - tb.x) / d.z) / 0.2f;
            float lt3 = __logf((tb.w - tb.y) / d.w) / 0.2f;
            float4 ld = loc4[ip];
            float dv[4] = {ld.x - lt0, ld.y - lt1, ld.z - lt2, ld.w - lt3};
            float acc = 0.0f;
#pragma unroll
            for (int i = 0; i < 4; i++) {
                float ad = fabsf(dv[i]);
                acc += (ad < 1.0f) ? 0.5f * dv[i] * dv[i] : (ad - 0.5f);
            }
            l_l = (double)acc;
        }
    }

    double wll = warp_sum_d(l_l);
    double wlc = warp_sum_d(l_c);
    unsigned wnp = warp_sum_u(npos);
    const int warp = tid >> 5, lane = tid & 31;
    if (lane == 0) { s_ll[warp] = wll; s_lc[warp] = wlc; s_np[warp] = wnp; }
    __syncthreads();
    if (tid == 0) {
        double tll = 0.0, tlc = 0.0; unsigned tnp = 0;
        for (int w = 0; w < 8; w++) { tll += s_ll[w]; tlc += s_lc[w]; tnp += s_np[w]; }
        if (tll != 0.0) atomicAdd(&g_loss_l, tll);
        if (tlc != 0.0) atomicAdd(&g_loss_c, tlc);
        if (tnp) atomicAdd(&g_numpos[b], (int)tnp);
    }
}

// ---------------- K3: top-K sum, register-resident radix-256 select ----------------
// grid BB blocks, 1024 threads; values live in registers (9/thread, zero-padded)
__global__ void __launch_bounds__(TKT, 1) k_topk() {
    __shared__ unsigned hist[256];
    __shared__ unsigned wsuf[8];
    __shared__ unsigned s_B, s_Krem;
    __shared__ double   ssum[TKT / 32];
    __shared__ unsigned scnt[TKT / 32];

    const int b = blockIdx.x;
    const int tid = threadIdx.x;
    const int lane = tid & 31, warp = tid >> 5;

    if (tid < NO) g_best_prior[b * NO + tid] = 0ULL;   // reset for next replay

    // load values into registers (coalesced); pad with 0.0 (provably safe)
    unsigned u[EPT];
#pragma unroll
    for (int k = 0; k < EPT; k++) {
        int i = tid + k * TKT;
        u[k] = (i < NP) ? __float_as_uint(g_hnm[(size_t)b * NP + i]) : 0u;
    }
    const int K = min(3 * g_numpos[b], NP);
    if (K <= 0) return;

    unsigned prefix = 0;
    unsigned Krem = (unsigned)K;

#pragma unroll
    for (int pass = 0; pass < 4; pass++) {
        const int shift = 24 - pass * 8;
        if (tid < 256) hist[tid] = 0;
        __syncthreads();

#pragma unroll
        for (int k = 0; k < EPT; k++) {
            bool match = (pass == 0) || ((u[k] >> (shift + 8)) == prefix);
            unsigned bin = match ? ((u[k] >> shift) & 0xFFu) : 0xFFFFFFFFu;
            unsigned mk = __match_any_sync(0xffffffffu, bin);
            if (match && lane == (__ffs(mk) - 1))
                atomicAdd(&hist[bin], (unsigned)__popc(mk));
        }
        __syncthreads();

        // exclusive suffix count per bin (8 warps over 256 bins)
        unsigned v = 0, s = 0;
        if (tid < 256) {
            v = hist[tid];
            s = v;
#pragma unroll
            for (int off = 1; off < 32; off <<= 1) {
                unsigned w = __shfl_down_sync(0xffffffffu, s, off);
                if (lane + off < 32) s += w;
            }
            if (lane == 0) wsuf[warp] = s;
        }
        __syncthreads();
        if (tid == 0) {
            unsigned acc = 0;
            for (int w = 7; w >= 0; w--) { unsigned t2 = wsuf[w]; wsuf[w] = acc; acc += t2; }
        }
        __syncthreads();
        if (tid < 256) {
            unsigned exc = (s - v) + wsuf[warp];   // candidates strictly above bin tid
            if (exc < Krem && Krem <= exc + v) { s_B = (unsigned)tid; s_Krem = Krem - exc; }
        }
        __syncthreads();
        prefix = (prefix << 8) | s_B;
        Krem = s_Krem;
    }

    // prefix = float bits of K-th largest value T (all hnm >= 0 -> uint-ordered)
    const unsigned T = prefix;
    double sum = 0.0;
    unsigned cgt = 0;
#pragma unroll
    for (int k = 0; k < EPT; k++) {
        if (u[k] > T) { sum += (double)__uint_as_float(u[k]); cgt++; }
    }
    sum = warp_sum_d(sum);
    cgt = warp_sum_u(cgt);
    if (lane == 0) { ssum[warp] = sum; scnt[warp] = cgt; }
    __syncthreads();
    if (tid == 0) {
        double tsum = 0.0; unsigned tcgt = 0;
        for (int w = 0; w < TKT / 32; w++) { tsum += ssum[w]; tcgt += scnt[w]; }
        tsum += (double)((unsigned)K - tcgt) * (double)__uint_as_float(T);
        atomicAdd(&g_loss_c, tsum);
    }
}

// ---------------- K4: finalize + reset accumulators for next replay ----------------
__global__ void k_fin(float* __restrict__ out) {
    __shared__ int ssum[4];
    const int tid = threadIdx.x;   // 128 threads
    int n = g_numpos[tid];
    g_numpos[tid] = 0;
    unsigned un = warp_sum_u((unsigned)n);
    if ((tid & 31) == 0) ssum[tid >> 5] = (int)un;
    __syncthreads();
    if (tid == 0) {
        int tot = ssum[0] + ssum[1] + ssum[2] + ssum[3];
        double N = (double)tot;
        out[0] = (float)(g_loss_l / N);
        out[1] = (float)(g_loss_c / N);
        g_loss_l = 0.0;
        g_loss_c = 0.0;
    }
}

// ---------------- launch ----------------
extern "C" void kernel_launch(void* const* d_in, const int* in_sizes, int n_in,
                              void* d_out, int out_size) {
    const float4* loc4     = (const float4*)d_in[0];
    const float*  conf     = (const float*)d_in[1];
    const float4* dbox4    = (const float4*)d_in[2];
    const float*  targets  = (const float*)d_in[3];
    float* out = (float*)d_out;

    k_match<<<dim3(NXB, BB), PBLK>>>(dbox4, targets);
    k_loss<<<dim3(NXB, BB), PBLK>>>(loc4, conf, dbox4, targets);
    k_topk<<<BB, TKT>>>();
    k_fin<<<1, BB>>>(out);
}